// round 2
// baseline (speedup 1.0000x reference)
#include <cuda_runtime.h>
#include <math.h>
#include <stdint.h>

typedef unsigned long long u64;

#define NB   8
#define CIN  64
#define CO   128
#define HH0  256
#define WW0  256
#define HWSZ 65536
#define HD   128   // H/2
#define WD   128   // W/2

// ---------------- scratch (static device globals; no runtime alloc) ----------------
__device__ float g_wsn[CO*CIN*9];
__device__ float g_ratio[NB*HWSZ];
__device__ float g_mvalid[NB*HWSZ];
__device__ float g_y[(size_t)NB*CO*HWSZ];           // conv out, then GDN in-place
__device__ float g_lor[(size_t)NB*CO*HD*WW0];
__device__ float g_hir[(size_t)NB*CO*HD*WW0];
__device__ float g_mlo[NB*HD*WW0];
__device__ float g_mhi[NB*HD*WW0];

__constant__ float c_H0[9] = {
    0.026748757410810f, -0.016864118442875f, -0.078223266528990f,
    0.266864118442875f,  0.602949018236360f,  0.266864118442875f,
   -0.078223266528990f, -0.016864118442875f,  0.026748757410810f};
__constant__ float c_H1[7] = {
    0.091271763114250f, -0.057543526228500f, -0.591271763114250f,
    1.115087052457000f, -0.591271763114250f, -0.057543526228500f,
    0.091271763114250f};

// output offsets: (ll, m_ll, lh, hl, hh, m_lh, m_hl, m_hh)
#define SZ_BAND ((size_t)NB*CO*HD*WD)
#define SZ_MASK ((size_t)NB*HD*WD)
#define OFS_LL   ((size_t)0)
#define OFS_MLL  (OFS_LL  + SZ_BAND)
#define OFS_LH   (OFS_MLL + SZ_MASK)
#define OFS_HL   (OFS_LH  + SZ_BAND)
#define OFS_HH   (OFS_HL  + SZ_BAND)
#define OFS_MLH  (OFS_HH  + SZ_BAND)
#define OFS_MHL  (OFS_MLH + SZ_MASK)
#define OFS_MHH  (OFS_MHL + SZ_MASK)

__device__ __forceinline__ int refl(int j, int n) {
    if (j < 0) j = -j;
    if (j >= n) j = 2*n - 2 - j;
    return j;
}

// ---- packed f32x2 helpers (FFMA2 path; ptxas never emits this from C++) ----
__device__ __forceinline__ u64 pk2(float lo, float hi) {
    u64 d;
    asm("mov.b64 %0,{%1,%2};" : "=l"(d) : "f"(lo), "f"(hi));
    return d;
}
__device__ __forceinline__ void upk2(u64 d, float& lo, float& hi) {
    asm("mov.b64 {%0,%1},%2;" : "=f"(lo), "=f"(hi) : "l"(d));
}
__device__ __forceinline__ void fma2(u64& d, u64 a, u64 b) {
    asm("fma.rn.f32x2 %0,%1,%2,%3;" : "=l"(d) : "l"(a), "l"(b), "l"(d));
}

// ---------------- K0: spectral norm -> g_wsn ----------------
__global__ void k_sigma(const float* __restrict__ w, const float* __restrict__ u) {
    __shared__ float sv[576];
    __shared__ float red[576];
    __shared__ float s_bcast;
    int t = threadIdx.x;           // 576 threads

    float vj = 0.f;
    for (int o = 0; o < CO; ++o) vj += w[o*576 + t] * u[o];
    red[t] = vj*vj;
    sv[t] = vj;
    __syncthreads();
    if (t == 0) {
        float s = 0.f;
        for (int i = 0; i < 576; ++i) s += red[i];
        s_bcast = 1.f / (sqrtf(s) + 1e-12f);
    }
    __syncthreads();
    float vn = sv[t] * s_bcast;
    __syncthreads();
    sv[t] = vn;
    __syncthreads();

    if (t < CO) {
        float s = 0.f;
        for (int j = 0; j < 576; ++j) s += w[t*576 + j] * sv[j];
        red[t] = s*s;
    }
    __syncthreads();
    if (t == 0) {
        float s = 0.f;
        for (int i = 0; i < CO; ++i) s += red[i];
        s_bcast = 1.f / sqrtf(s);   // 1/sigma
    }
    __syncthreads();
    float inv_sigma = s_bcast;
    for (int i = t; i < CO*CIN*9; i += 576) g_wsn[i] = w[i] * inv_sigma;
}

// ---------------- K1: mask 3x3 box -> ratio + valid ----------------
__global__ void k_ratio(const float* __restrict__ mask) {
    int idx = blockIdx.x*256 + threadIdx.x;            // over NB*HWSZ
    int b = idx >> 16;
    int hw = idx & 65535;
    int h = hw >> 8, wx = hw & 255;
    const float* mb = mask + (size_t)b*HWSZ;
    float s = 0.f;
    #pragma unroll
    for (int dh = -1; dh <= 1; ++dh) {
        int h2 = h + dh;
        if (h2 < 0 || h2 >= HH0) continue;
        #pragma unroll
        for (int dw = -1; dw <= 1; ++dw) {
            int w2 = wx + dw;
            if (w2 < 0 || w2 >= WW0) continue;
            s += mb[h2*WW0 + w2];
        }
    }
    bool valid = s > 0.f;
    g_mvalid[idx] = valid ? 1.f : 0.f;
    g_ratio[idx]  = valid ? 9.f / fmaxf(s, 1e-8f) : 0.f;
}

// ---------------- K2: 3x3 partial conv, FFMA2 (pixel pairs) ----------------
// block: 32 o-chan x 8 h x 64 w, 256 threads; thread: 8 o x 4 pixel-pairs
__global__ void __launch_bounds__(256, 1) k_conv(const float* __restrict__ x,
                                                 const float* __restrict__ mask,
                                                 const float* __restrict__ bias) {
    __shared__ float xs[10][68];
    __shared__ u64  ws2[32*9];    // duplicated (w,w) pairs

    int wt = blockIdx.x * 64;
    int ht = blockIdx.y * 8;
    int bo = blockIdx.z;
    int b  = bo >> 2;
    int ob = (bo & 3) * 32;

    int t  = threadIdx.x;
    int wg = t & 7, hg = (t >> 3) & 7, og = t >> 6;

    u64 acc2[8][4];
    #pragma unroll
    for (int i = 0; i < 8; ++i)
        #pragma unroll
        for (int j = 0; j < 4; ++j) acc2[i][j] = pk2(0.f, 0.f);

    const float* xb = x    + (size_t)b*CIN*HWSZ;
    const float* mb = mask + (size_t)b*HWSZ;

    for (int c = 0; c < CIN; ++c) {
        __syncthreads();
        const float* xc = xb + (size_t)c*HWSZ;
        for (int i = t; i < 10*66; i += 256) {
            int r = i / 66, cc = i % 66;
            int h = ht - 1 + r, wx = wt - 1 + cc;
            float v = 0.f;
            if (h >= 0 && h < HH0 && wx >= 0 && wx < WW0)
                v = xc[h*WW0 + wx] * mb[h*WW0 + wx];
            xs[r][cc] = v;
        }
        for (int i = t; i < 288; i += 256) {
            int o = i / 9, k = i % 9;
            float wv = g_wsn[((size_t)(ob + o)*CIN + c)*9 + k];
            ws2[i] = pk2(wv, wv);
        }
        __syncthreads();

        // per row: 5 even-aligned pairs E[0..4] + 4 odd pairs O[0..3]
        u64 E[3][5], O[3][4];
        #pragma unroll
        for (int r = 0; r < 3; ++r) {
            float e[10];
            #pragma unroll
            for (int j = 0; j < 5; ++j) {
                E[r][j] = *(const u64*)&xs[hg + r][wg*8 + 2*j];
                upk2(E[r][j], e[2*j], e[2*j + 1]);
            }
            #pragma unroll
            for (int j = 0; j < 4; ++j)
                O[r][j] = pk2(e[2*j + 1], e[2*j + 2]);
        }

        #pragma unroll
        for (int oo = 0; oo < 8; ++oo) {
            const u64* wp = &ws2[(og*8 + oo)*9];
            u64 w0 = wp[0], w1 = wp[1], w2 = wp[2];
            u64 w3 = wp[3], w4 = wp[4], w5 = wp[5];
            u64 w6 = wp[6], w7 = wp[7], w8 = wp[8];
            #pragma unroll
            for (int jj = 0; jj < 4; ++jj) {
                u64 a = acc2[oo][jj];
                fma2(a, w0, E[0][jj]); fma2(a, w1, O[0][jj]); fma2(a, w2, E[0][jj+1]);
                fma2(a, w3, E[1][jj]); fma2(a, w4, O[1][jj]); fma2(a, w5, E[1][jj+1]);
                fma2(a, w6, E[2][jj]); fma2(a, w7, O[2][jj]); fma2(a, w8, E[2][jj+1]);
                acc2[oo][jj] = a;
            }
        }
    }

    // epilogue: renormalize + bias + mask
    int h = ht + hg;
    float rt[8];
    #pragma unroll
    for (int p = 0; p < 8; ++p) {
        int wx = wt + wg*8 + p;
        rt[p] = g_ratio[((size_t)b*HH0 + h)*WW0 + wx];
    }
    #pragma unroll
    for (int oo = 0; oo < 8; ++oo) {
        int o = ob + og*8 + oo;
        float bv = bias[o];
        float* yp = g_y + (((size_t)b*CO + o)*HH0 + h)*WW0 + wt + wg*8;
        #pragma unroll
        for (int jj = 0; jj < 4; ++jj) {
            float v0, v1;
            upk2(acc2[oo][jj], v0, v1);
            float r0 = rt[2*jj], r1 = rt[2*jj + 1];
            float2 outp;
            outp.x = (r0 > 0.f) ? v0*r0 + bv : 0.f;
            outp.y = (r1 > 0.f) ? v1*r1 + bv : 0.f;
            *(float2*)&yp[2*jj] = outp;
        }
    }
}

// ---------------- K3: GDN (in-place on g_y), FFMA2 tiled GEMM ----------------
// thread (px,oy): pixels {2px, 2px+1} + 32j (j=0..3), outputs oy*8..oy*8+7
__global__ void __launch_bounds__(256, 1) k_gdn(const float* __restrict__ gamma,
                                                const float* __restrict__ beta) {
    __shared__ float zs[16][128];
    __shared__ u64  gs2[128][17];   // duplicated (g,g) pairs, padded

    size_t p0 = (size_t)blockIdx.x * 128;     // global pixel tile (b*HWSZ + hw)
    int b   = (int)(p0 >> 16);
    int hw0 = (int)(p0 & 65535);
    int t = threadIdx.x;
    int px = t & 15, oy = t >> 4;

    u64 acc2[8][4];
    #pragma unroll
    for (int i = 0; i < 8; ++i)
        #pragma unroll
        for (int j = 0; j < 4; ++j) acc2[i][j] = pk2(0.f, 0.f);

    float* yb = g_y + (size_t)b*CO*HWSZ + hw0;

    for (int c0 = 0; c0 < CO; c0 += 16) {
        __syncthreads();
        for (int i = t; i < 2048; i += 256) {        // z = x^2 chunk [16][128]
            int k = i >> 7, p = i & 127;
            float v = yb[(size_t)(c0 + k)*HWSZ + p];
            zs[k][p] = v*v;
        }
        for (int i = t; i < 2048; i += 256) {        // gamma chunk [128][16], duplicated
            int o = i >> 4, k = i & 15;
            float gv = gamma[o*CO + c0 + k];
            gs2[o][k] = pk2(gv, gv);
        }
        __syncthreads();
        #pragma unroll
        for (int k = 0; k < 16; ++k) {
            u64 bb[4];
            #pragma unroll
            for (int j = 0; j < 4; ++j)
                bb[j] = *(const u64*)&zs[k][2*px + 32*j];
            #pragma unroll
            for (int i = 0; i < 8; ++i) {
                u64 a = gs2[oy*8 + i][k];
                #pragma unroll
                for (int j = 0; j < 4; ++j)
                    fma2(acc2[i][j], a, bb[j]);
            }
        }
    }

    #pragma unroll
    for (int i = 0; i < 8; ++i) {
        int o = oy*8 + i;
        float bo = beta[o];
        #pragma unroll
        for (int j = 0; j < 4; ++j) {
            int p = 2*px + 32*j;
            size_t ad = (size_t)o*HWSZ + p;
            float s0, s1;
            upk2(acc2[i][j], s0, s1);
            float x0 = yb[ad], x1 = yb[ad + 1];
            float m0 = g_mvalid[p0 + p], m1 = g_mvalid[p0 + p + 1];
            yb[ad]     = x0 * rsqrtf(bo + s0) * m0;
            yb[ad + 1] = x1 * rsqrtf(bo + s1) * m1;
        }
    }
}

// ---------------- K4: DWT row filters (H axis, stride 2, reflect) ----------------
__global__ void k_dwt_rows() {
    size_t idx = (size_t)blockIdx.x*256 + threadIdx.x;  // [B*C][HD][W]
    int wx = (int)(idx & 255);
    int hr = (int)((idx >> 8) & 127);
    int bc = (int)(idx >> 15);
    const float* col = g_y + (size_t)bc*HWSZ + wx;
    float r[9];
    #pragma unroll
    for (int k = 0; k < 9; ++k)
        r[k] = col[refl(2*hr + k - 4, HH0) * WW0];
    float lo = 0.f, hi = 0.f;
    #pragma unroll
    for (int k = 0; k < 9; ++k) lo += c_H0[k]*r[k];
    #pragma unroll
    for (int k = 0; k < 7; ++k) hi += c_H1[k]*r[k+1];
    g_lor[idx] = lo;
    g_hir[idx] = hi;
}

// ---------------- K5: DWT col filters -> 4 bands straight to d_out ----------------
__global__ void k_dwt_cols(float* __restrict__ out) {
    size_t idx = (size_t)blockIdx.x*256 + threadIdx.x;  // [B*C][HD][WD]
    int wr = (int)(idx & 127);
    int hr = (int)((idx >> 7) & 127);
    int bc = (int)(idx >> 14);
    const float* lrow = g_lor + ((size_t)bc*HD + hr)*WW0;
    const float* hrow = g_hir + ((size_t)bc*HD + hr)*WW0;
    float rl[9], rh[9];
    #pragma unroll
    for (int k = 0; k < 9; ++k) {
        int j = refl(2*wr + k - 4, WW0);
        rl[k] = lrow[j];
        rh[k] = hrow[j];
    }
    float ll = 0.f, lh = 0.f, hl = 0.f, hh = 0.f;
    #pragma unroll
    for (int k = 0; k < 9; ++k) { ll += c_H0[k]*rl[k]; hl += c_H0[k]*rh[k]; }
    #pragma unroll
    for (int k = 0; k < 7; ++k) { lh += c_H1[k]*rl[k+1]; hh += c_H1[k]*rh[k+1]; }
    out[OFS_LL + idx] = ll;
    out[OFS_LH + idx] = lh;
    out[OFS_HL + idx] = hl;
    out[OFS_HH + idx] = hh;
}

// ---------------- K6: mask downsample along H ----------------
__global__ void k_mask_rows() {
    int idx = blockIdx.x*256 + threadIdx.x;   // [B][HD][W]
    int wx = idx & 255;
    int hr = (idx >> 8) & 127;
    int b  = idx >> 15;
    const float* mb = g_mvalid + (size_t)b*HWSZ + wx;
    float s9 = 0.f, s7 = 0.f;
    #pragma unroll
    for (int k = 0; k < 9; ++k) {
        float v = mb[refl(2*hr + k - 4, HH0) * WW0];
        s9 += v;
        if (k >= 1 && k <= 7) s7 += v;
    }
    g_mlo[idx] = (s9 > 0.f) ? 1.f : 0.f;
    g_mhi[idx] = (s7 > 0.f) ? 1.f : 0.f;
}

// ---------------- K7: mask downsample along W -> d_out ----------------
__global__ void k_mask_cols(float* __restrict__ out) {
    int idx = blockIdx.x*256 + threadIdx.x;   // [B][HD][WD]
    int wr = idx & 127;
    int hr = (idx >> 7) & 127;
    int b  = idx >> 14;
    const float* lrow = g_mlo + ((size_t)b*HD + hr)*WW0;
    const float* hrow = g_mhi + ((size_t)b*HD + hr)*WW0;
    float s9l = 0.f, s7l = 0.f, s9h = 0.f, s7h = 0.f;
    #pragma unroll
    for (int k = 0; k < 9; ++k) {
        int j = refl(2*wr + k - 4, WW0);
        float vl = lrow[j], vh = hrow[j];
        s9l += vl; s9h += vh;
        if (k >= 1 && k <= 7) { s7l += vl; s7h += vh; }
    }
    out[OFS_MLL + idx] = (s9l > 0.f) ? 1.f : 0.f;
    out[OFS_MLH + idx] = (s7l > 0.f) ? 1.f : 0.f;
    out[OFS_MHL + idx] = (s9h > 0.f) ? 1.f : 0.f;
    out[OFS_MHH + idx] = (s7h > 0.f) ? 1.f : 0.f;
}

// ---------------- launch ----------------
extern "C" void kernel_launch(void* const* d_in, const int* in_sizes, int n_in,
                              void* d_out, int out_size) {
    const float* tensor = (const float*)d_in[0];
    const float* mask   = (const float*)d_in[1];
    const float* weight = (const float*)d_in[2];
    const float* bias   = (const float*)d_in[3];
    const float* u      = (const float*)d_in[4];
    const float* beta   = (const float*)d_in[5];
    const float* gamma  = (const float*)d_in[6];
    float* out = (float*)d_out;

    k_sigma<<<1, 576>>>(weight, u);
    k_ratio<<<(NB*HWSZ)/256, 256>>>(mask);
    k_conv<<<dim3(4, 32, NB*4), 256>>>(tensor, mask, bias);
    k_gdn<<<(NB*HWSZ)/128, 256>>>(gamma, beta);
    k_dwt_rows<<<(int)(((size_t)NB*CO*HD*WW0)/256), 256>>>();
    k_dwt_cols<<<(int)(((size_t)NB*CO*HD*WD)/256), 256>>>(out);
    k_mask_rows<<<(NB*HD*WW0)/256, 256>>>();
    k_mask_cols<<<(NB*HD*WD)/256, 256>>>(out);
}

// round 5
// speedup vs baseline: 2.7062x; 2.7062x over previous
#include <cuda_runtime.h>
#include <cuda_bf16.h>
#include <math.h>
#include <stdint.h>

#define NB   8
#define CIN  64
#define CO   128
#define HH0  256
#define WW0  256
#define HWSZ 65536
#define HD   128
#define WD   128

// ---------------- scratch ----------------
__device__ float g_wsn[CO*CIN*9];
__device__ unsigned char g_wB[9*34816];     // per-tap [hi|lo][64 c-rows x 272B (128 o bf16 + pad)]
__device__ float g_ratio[NB*HWSZ];
__device__ float g_mvalid[NB*HWSZ];
__device__ float g_y[(size_t)NB*CO*HWSZ];
__device__ float g_lor[(size_t)NB*CO*HD*WW0];
__device__ float g_hir[(size_t)NB*CO*HD*WW0];
__device__ float g_mlo[NB*HD*WW0];
__device__ float g_mhi[NB*HD*WW0];

__constant__ float c_H0[9] = {
    0.026748757410810f, -0.016864118442875f, -0.078223266528990f,
    0.266864118442875f,  0.602949018236360f,  0.266864118442875f,
   -0.078223266528990f, -0.016864118442875f,  0.026748757410810f};
__constant__ float c_H1[7] = {
    0.091271763114250f, -0.057543526228500f, -0.591271763114250f,
    1.115087052457000f, -0.591271763114250f, -0.057543526228500f,
    0.091271763114250f};

#define SZ_BAND ((size_t)NB*CO*HD*WD)
#define SZ_MASK ((size_t)NB*HD*WD)
#define OFS_LL   ((size_t)0)
#define OFS_MLL  (OFS_LL  + SZ_BAND)
#define OFS_LH   (OFS_MLL + SZ_MASK)
#define OFS_HL   (OFS_LH  + SZ_BAND)
#define OFS_HH   (OFS_HL  + SZ_BAND)
#define OFS_MLH  (OFS_HH  + SZ_BAND)
#define OFS_MHL  (OFS_MLH + SZ_MASK)
#define OFS_MHH  (OFS_MHL + SZ_MASK)

__device__ __forceinline__ int refl(int j, int n) {
    if (j < 0) j = -j;
    if (j >= n) j = 2*n - 2 - j;
    return j;
}

// ---------------- mma.sync / ldmatrix / cp.async helpers (baseline PTX, sm_80+) ----------
__device__ __forceinline__ uint32_t smem_u32(const void* p) {
    uint32_t a;
    asm("{ .reg .u64 t; cvta.to.shared.u64 t, %1; cvt.u32.u64 %0, t; }" : "=r"(a) : "l"(p));
    return a;
}
__device__ __forceinline__ void ldsm4(uint32_t* r, uint32_t a) {
    asm volatile("ldmatrix.sync.aligned.m8n8.x4.shared.b16 {%0,%1,%2,%3}, [%4];"
        : "=r"(r[0]), "=r"(r[1]), "=r"(r[2]), "=r"(r[3]) : "r"(a));
}
__device__ __forceinline__ void ldsm4t(uint32_t* r, uint32_t a) {
    asm volatile("ldmatrix.sync.aligned.m8n8.x4.trans.shared.b16 {%0,%1,%2,%3}, [%4];"
        : "=r"(r[0]), "=r"(r[1]), "=r"(r[2]), "=r"(r[3]) : "r"(a));
}
__device__ __forceinline__ void mma16816(float* c, const uint32_t* a, const uint32_t* b) {
    asm volatile("mma.sync.aligned.m16n8k16.row.col.f32.bf16.bf16.f32 "
        "{%0,%1,%2,%3},{%4,%5,%6,%7},{%8,%9},{%0,%1,%2,%3};"
        : "+f"(c[0]), "+f"(c[1]), "+f"(c[2]), "+f"(c[3])
        : "r"(a[0]), "r"(a[1]), "r"(a[2]), "r"(a[3]), "r"(b[0]), "r"(b[1]));
}
__device__ __forceinline__ void cpa16(uint32_t s, const void* g) {
    asm volatile("cp.async.cg.shared.global [%0], [%1], 16;" :: "r"(s), "l"(g) : "memory");
}
__device__ __forceinline__ void cpa_commit() {
    asm volatile("cp.async.commit_group;" ::: "memory");
}
__device__ __forceinline__ void cpa_wait1() {
    asm volatile("cp.async.wait_group 1;" ::: "memory");
}

// ---------------- K0: spectral norm -> g_wsn ----------------
__global__ void k_sigma(const float* __restrict__ w, const float* __restrict__ u) {
    __shared__ float sv[576];
    __shared__ float red[576];
    __shared__ float s_bcast;
    int t = threadIdx.x;

    float vj = 0.f;
    for (int o = 0; o < CO; ++o) vj += w[o*576 + t] * u[o];
    red[t] = vj*vj;
    sv[t] = vj;
    __syncthreads();
    if (t == 0) {
        float s = 0.f;
        for (int i = 0; i < 576; ++i) s += red[i];
        s_bcast = 1.f / (sqrtf(s) + 1e-12f);
    }
    __syncthreads();
    float vn = sv[t] * s_bcast;
    __syncthreads();
    sv[t] = vn;
    __syncthreads();

    if (t < CO) {
        float s = 0.f;
        for (int j = 0; j < 576; ++j) s += w[t*576 + j] * sv[j];
        red[t] = s*s;
    }
    __syncthreads();
    if (t == 0) {
        float s = 0.f;
        for (int i = 0; i < CO; ++i) s += red[i];
        s_bcast = 1.f / sqrtf(s);
    }
    __syncthreads();
    float inv_sigma = s_bcast;
    for (int i = t; i < CO*CIN*9; i += 576) g_wsn[i] = w[i] * inv_sigma;
}

// ---------------- K0b: weights -> per-tap [c][o] bf16 hi/lo rows (272B stride) --------
__global__ void k_prepw() {
    int idx = blockIdx.x*256 + threadIdx.x;   // 73728 = 9 taps * 64c * 128o
    if (idx >= 9*CIN*CO) return;
    int q = idx >> 13;
    int rem = idx & 8191;
    int c = rem >> 7;
    int o = rem & 127;
    float v = g_wsn[(o*CIN + c)*9 + q];
    __nv_bfloat16 hi = __float2bfloat16(v);
    __nv_bfloat16 lo = __float2bfloat16(v - __bfloat162float(hi));
    size_t base = (size_t)q*34816;
    *(__nv_bfloat16*)(g_wB + base +         c*272 + o*2) = hi;
    *(__nv_bfloat16*)(g_wB + base + 17408 + c*272 + o*2) = lo;
}

// ---------------- K1: mask 3x3 box -> ratio + valid ----------------
__global__ void k_ratio(const float* __restrict__ mask) {
    int idx = blockIdx.x*256 + threadIdx.x;
    int b = idx >> 16;
    int hw = idx & 65535;
    int h = hw >> 8, wx = hw & 255;
    const float* mb = mask + (size_t)b*HWSZ;
    float s = 0.f;
    #pragma unroll
    for (int dh = -1; dh <= 1; ++dh) {
        int h2 = h + dh;
        if (h2 < 0 || h2 >= HH0) continue;
        #pragma unroll
        for (int dw = -1; dw <= 1; ++dw) {
            int w2 = wx + dw;
            if (w2 < 0 || w2 >= WW0) continue;
            s += mb[h2*WW0 + w2];
        }
    }
    bool valid = s > 0.f;
    g_mvalid[idx] = valid ? 1.f : 0.f;
    g_ratio[idx]  = valid ? 9.f / fmaxf(s, 1e-8f) : 0.f;
}

// ---------------- K2: mma.sync implicit-GEMM conv (bf16 3-term split) ----------------
// CTA: 128 px (2h x 64w) as M, 128 o as N, K = 9 taps x 64 c.
// Patch smem: [4 rows][66 w] pixel-rows of 64 c bf16, row stride 144B (conflict-free ldmatrix).
// Weights smem: per tap [64 c-rows][128 o], row stride 272B, cp.async double-buffered.
#define P_HI 0
#define P_LO 38016
#define BW0  76032
#define BW1  110848
#define SMEM_MMA 145664

extern __shared__ char smc[];

__global__ void __launch_bounds__(256) k_conv_mma(const float* __restrict__ x,
                                                  const float* __restrict__ mask,
                                                  const float* __restrict__ bias) {
    uint32_t sb = smem_u32(smc);
    int t = threadIdx.x, l = t & 31, wid = t >> 5;
    int w0 = blockIdx.x * 64, h0 = blockIdx.y * 2, b = blockIdx.z;
    int warp_m = wid & 1;          // pixel half: r = warp_m
    int warp_n = wid >> 1;         // o block of 32

    // ---- patch fill: 64c x 4rows x 66w of (x*mask), bf16 hi/lo ----
    for (int i = t; i < 16896; i += 256) {
        int w = i % 66;
        int rem = i / 66;
        int r = rem & 3;
        int c = rem >> 2;
        int h = h0 - 1 + r, wx = w0 - 1 + w;
        float v = 0.f;
        if (h >= 0 && h < HH0 && wx >= 0 && wx < WW0)
            v = x[(((size_t)b*CIN + c)*HH0 + h)*WW0 + wx]
              * mask[((size_t)b*HH0 + h)*WW0 + wx];
        __nv_bfloat16 hi = __float2bfloat16(v);
        __nv_bfloat16 lo = __float2bfloat16(v - __bfloat162float(hi));
        int off = (r*66 + w)*144 + c*2;
        *(__nv_bfloat16*)(smc + P_HI + off) = hi;
        *(__nv_bfloat16*)(smc + P_LO + off) = lo;
    }

    // ---- prefetch taps 0,1 via cp.async ----
    for (int i = t; i < 2176; i += 256)
        cpa16(sb + BW0 + i*16, g_wB + (size_t)0*34816 + i*16);
    cpa_commit();
    for (int i = t; i < 2176; i += 256)
        cpa16(sb + BW1 + i*16, g_wB + (size_t)1*34816 + i*16);
    cpa_commit();
    cpa_wait1();
    __syncthreads();

    float acc[4][4][4];
    #pragma unroll
    for (int mi = 0; mi < 4; ++mi)
        #pragma unroll
        for (int ni = 0; ni < 4; ++ni)
            #pragma unroll
            for (int k = 0; k < 4; ++k) acc[mi][ni][k] = 0.f;

    int lane15 = l & 15;
    int kh8 = ((l >> 4) & 1) * 8;      // A: k-half select
    int noff = ((l >> 4) & 1) * 8;     // B: n-block select

    for (int q = 0; q < 9; ++q) {
        int kh = q / 3, kw = q - kh*3;
        uint32_t bwbase = sb + ((q & 1) ? BW1 : BW0);
        int prow0 = ((warp_m + kh)*66 + kw) * 144;

        #pragma unroll
        for (int ks = 0; ks < 4; ++ks) {
            int k0 = ks * 16;
            uint32_t aH[4][4], aL[4][4];
            #pragma unroll
            for (int mi = 0; mi < 4; ++mi) {
                uint32_t off = (uint32_t)(prow0 + (mi*16 + lane15)*144 + (k0 + kh8)*2);
                ldsm4(aH[mi], sb + P_HI + off);
                ldsm4(aL[mi], sb + P_LO + off);
            }
            uint32_t bH[2][4], bL[2][4];
            #pragma unroll
            for (int n2 = 0; n2 < 2; ++n2) {
                uint32_t boff = (uint32_t)((k0 + lane15)*272 + (warp_n*32 + n2*16 + noff)*2);
                ldsm4t(bH[n2], bwbase + boff);
                ldsm4t(bL[n2], bwbase + 17408 + boff);
            }
            #pragma unroll
            for (int mi = 0; mi < 4; ++mi)
                #pragma unroll
                for (int ni = 0; ni < 4; ++ni) {
                    const uint32_t* bh = &bH[ni >> 1][(ni & 1)*2];
                    const uint32_t* bl = &bL[ni >> 1][(ni & 1)*2];
                    mma16816(acc[mi][ni], aH[mi], bh);
                    mma16816(acc[mi][ni], aH[mi], bl);
                    mma16816(acc[mi][ni], aL[mi], bh);
                }
        }

        __syncthreads();    // all warps done reading weight buffer (q&1) before overwrite
        if (q < 8) {
            if (q < 7) {
                uint32_t dst = sb + ((q & 1) ? BW1 : BW0);
                const unsigned char* src = g_wB + (size_t)(q + 2)*34816;
                for (int i = t; i < 2176; i += 256)
                    cpa16(dst + i*16, src + i*16);
            }
            cpa_commit();
            cpa_wait1();
            __syncthreads();
        }
    }

    // ---- epilogue: frags -> Dsmem[o:128][px:130] -> renorm+bias -> g_y ----
    __syncthreads();
    float* D = (float*)smc;
    #pragma unroll
    for (int mi = 0; mi < 4; ++mi)
        #pragma unroll
        for (int ni = 0; ni < 4; ++ni) {
            int px = warp_m*64 + mi*16 + (l >> 2);
            int o  = warp_n*32 + ni*8 + 2*(l & 3);
            D[o*130 + px]           = acc[mi][ni][0];
            D[(o + 1)*130 + px]     = acc[mi][ni][1];
            D[o*130 + px + 8]       = acc[mi][ni][2];
            D[(o + 1)*130 + px + 8] = acc[mi][ni][3];
        }
    __syncthreads();

    int wp = t & 63, og = t >> 6;
    #pragma unroll
    for (int r = 0; r < 2; ++r) {
        int h = h0 + r;
        int wg = w0 + wp;
        float rt = g_ratio[((size_t)b*HH0 + h)*WW0 + wg];
        #pragma unroll 8
        for (int oo = 0; oo < 32; ++oo) {
            int o = oo*4 + og;
            float v = D[o*130 + r*64 + wp];
            g_y[(((size_t)b*CO + o)*HH0 + h)*WW0 + wg] = (rt > 0.f) ? v*rt + bias[o] : 0.f;
        }
    }
}

// ---------------- K3: GDN (in-place), scalar tiled GEMM ----------------
__global__ void __launch_bounds__(256) k_gdn(const float* __restrict__ gamma,
                                             const float* __restrict__ beta) {
    __shared__ float zs[16][128];
    __shared__ float gs[128][17];

    size_t p0 = (size_t)blockIdx.x * 128;
    int b   = (int)(p0 >> 16);
    int hw0 = (int)(p0 & 65535);
    int t = threadIdx.x;
    int px = t & 15, oy = t >> 4;

    float acc[8][8];
    #pragma unroll
    for (int i = 0; i < 8; ++i)
        #pragma unroll
        for (int j = 0; j < 8; ++j) acc[i][j] = 0.f;

    float* yb = g_y + (size_t)b*CO*HWSZ + hw0;

    for (int c0 = 0; c0 < CO; c0 += 16) {
        __syncthreads();
        for (int i = t; i < 2048; i += 256) {
            int k = i >> 7, p = i & 127;
            float v = yb[(size_t)(c0 + k)*HWSZ + p];
            zs[k][p] = v*v;
        }
        for (int i = t; i < 2048; i += 256) {
            int o = i >> 4, k = i & 15;
            gs[o][k] = gamma[o*CO + c0 + k];
        }
        __syncthreads();
        #pragma unroll
        for (int k = 0; k < 16; ++k) {
            float a[8], bb[8];
            #pragma unroll
            for (int i = 0; i < 8; ++i) a[i] = gs[oy*8 + i][k];
            #pragma unroll
            for (int j = 0; j < 8; ++j) bb[j] = zs[k][px + 16*j];
            #pragma unroll
            for (int i = 0; i < 8; ++i)
                #pragma unroll
                for (int j = 0; j < 8; ++j) acc[i][j] += a[i]*bb[j];
        }
    }

    #pragma unroll
    for (int i = 0; i < 8; ++i) {
        int o = oy*8 + i;
        float bo = beta[o];
        #pragma unroll
        for (int j = 0; j < 8; ++j) {
            int p = px + 16*j;
            size_t ad = (size_t)o*HWSZ + p;
            float xv = yb[ad];
            float mv = g_mvalid[p0 + p];
            yb[ad] = xv * rsqrtf(bo + acc[i][j]) * mv;
        }
    }
}

// ---------------- K4: DWT row filters ----------------
__global__ void k_dwt_rows() {
    size_t idx = (size_t)blockIdx.x*256 + threadIdx.x;
    int wx = (int)(idx & 255);
    int hr = (int)((idx >> 8) & 127);
    int bc = (int)(idx >> 15);
    const float* col = g_y + (size_t)bc*HWSZ + wx;
    float r[9];
    #pragma unroll
    for (int k = 0; k < 9; ++k)
        r[k] = col[refl(2*hr + k - 4, HH0) * WW0];
    float lo = 0.f, hi = 0.f;
    #pragma unroll
    for (int k = 0; k < 9; ++k) lo += c_H0[k]*r[k];
    #pragma unroll
    for (int k = 0; k < 7; ++k) hi += c_H1[k]*r[k+1];
    g_lor[idx] = lo;
    g_hir[idx] = hi;
}

// ---------------- K5: DWT col filters -> 4 bands ----------------
__global__ void k_dwt_cols(float* __restrict__ out) {
    size_t idx = (size_t)blockIdx.x*256 + threadIdx.x;
    int wr = (int)(idx & 127);
    int hr = (int)((idx >> 7) & 127);
    int bc = (int)(idx >> 14);
    const float* lrow = g_lor + ((size_t)bc*HD + hr)*WW0;
    const float* hrow = g_hir + ((size_t)bc*HD + hr)*WW0;
    float rl[9], rh[9];
    #pragma unroll
    for (int k = 0; k < 9; ++k) {
        int j = refl(2*wr + k - 4, WW0);
        rl[k] = lrow[j];
        rh[k] = hrow[j];
    }
    float ll = 0.f, lh = 0.f, hl = 0.f, hh = 0.f;
    #pragma unroll
    for (int k = 0; k < 9; ++k) { ll += c_H0[k]*rl[k]; hl += c_H0[k]*rh[k]; }
    #pragma unroll
    for (int k = 0; k < 7; ++k) { lh += c_H1[k]*rl[k+1]; hh += c_H1[k]*rh[k+1]; }
    out[OFS_LL + idx] = ll;
    out[OFS_LH + idx] = lh;
    out[OFS_HL + idx] = hl;
    out[OFS_HH + idx] = hh;
}

// ---------------- K6: mask downsample along H ----------------
__global__ void k_mask_rows() {
    int idx = blockIdx.x*256 + threadIdx.x;
    int wx = idx & 255;
    int hr = (idx >> 8) & 127;
    int b  = idx >> 15;
    const float* mb = g_mvalid + (size_t)b*HWSZ + wx;
    float s9 = 0.f, s7 = 0.f;
    #pragma unroll
    for (int k = 0; k < 9; ++k) {
        float v = mb[refl(2*hr + k - 4, HH0) * WW0];
        s9 += v;
        if (k >= 1 && k <= 7) s7 += v;
    }
    g_mlo[idx] = (s9 > 0.f) ? 1.f : 0.f;
    g_mhi[idx] = (s7 > 0.f) ? 1.f : 0.f;
}

// ---------------- K7: mask downsample along W -> out ----------------
__global__ void k_mask_cols(float* __restrict__ out) {
    int idx = blockIdx.x*256 + threadIdx.x;
    int wr = idx & 127;
    int hr = (idx >> 7) & 127;
    int b  = idx >> 14;
    const float* lrow = g_mlo + ((size_t)b*HD + hr)*WW0;
    const float* hrow = g_mhi + ((size_t)b*HD + hr)*WW0;
    float s9l = 0.f, s7l = 0.f, s9h = 0.f, s7h = 0.f;
    #pragma unroll
    for (int k = 0; k < 9; ++k) {
        int j = refl(2*wr + k - 4, WW0);
        float vl = lrow[j], vh = hrow[j];
        s9l += vl; s9h += vh;
        if (k >= 1 && k <= 7) { s7l += vl; s7h += vh; }
    }
    out[OFS_MLL + idx] = (s9l > 0.f) ? 1.f : 0.f;
    out[OFS_MLH + idx] = (s7l > 0.f) ? 1.f : 0.f;
    out[OFS_MHL + idx] = (s9h > 0.f) ? 1.f : 0.f;
    out[OFS_MHH + idx] = (s7h > 0.f) ? 1.f : 0.f;
}

// ---------------- launch ----------------
extern "C" void kernel_launch(void* const* d_in, const int* in_sizes, int n_in,
                              void* d_out, int out_size) {
    const float* tensor = (const float*)d_in[0];
    const float* mask   = (const float*)d_in[1];
    const float* weight = (const float*)d_in[2];
    const float* bias   = (const float*)d_in[3];
    const float* u      = (const float*)d_in[4];
    const float* beta   = (const float*)d_in[5];
    const float* gamma  = (const float*)d_in[6];
    float* out = (float*)d_out;

    cudaFuncSetAttribute(k_conv_mma, cudaFuncAttributeMaxDynamicSharedMemorySize, SMEM_MMA);

    k_sigma<<<1, 576>>>(weight, u);
    k_prepw<<<288, 256>>>();
    k_ratio<<<(NB*HWSZ)/256, 256>>>(mask);
    k_conv_mma<<<dim3(4, 128, NB), 256, SMEM_MMA>>>(tensor, mask, bias);
    k_gdn<<<(NB*HWSZ)/128, 256>>>(gamma, beta);
    k_dwt_rows<<<(int)(((size_t)NB*CO*HD*WW0)/256), 256>>>();
    k_dwt_cols<<<(int)(((size_t)NB*CO*HD*WD)/256), 256>>>(out);
    k_mask_rows<<<(NB*HD*WW0)/256, 256>>>();
    k_mask_cols<<<(NB*HD*WD)/256, 256>>>(out);
}